// round 15
// baseline (speedup 1.0000x reference)
#include <cuda_runtime.h>
#include <cuda_fp16.h>
#include <cstdint>

#define DI __device__ __forceinline__

constexpr int C    = 128;
constexpr int T    = 4096;
constexpr int R    = 4096;
constexpr int NCTX = 8;
constexpr int TM   = 128;    // M rows per CTA
constexpr int NMT  = T / TM; // 32 m-tiles
constexpr int NT   = 32;     // 128-wide col tiles
constexpr int NG   = 2 * NT; // pass0 (rowsum) + pass1 (write)
constexpr int THREADS = 512;
constexpr int NSLOT = 6;     // B ring depth
constexpr int LEAD  = 4;     // producer lead distance

// normalized fp16 features; g_ft pre-scaled by log2(e) so exp(dot) = ex2(acc)
__device__ __align__(256) __half g_ft[T * C];                    // 1 MB
__device__ __align__(256) __half g_fr[(size_t)NCTX * C * R];     // 8 MB (L2-resident)

// SMEM: 6-slot B ring + mbarriers + reduction scratch
constexpr uint32_t SB_SZ   = 32768;
constexpr uint32_t SMBAR   = 196608;   // full[0..5] @ +0, empty[0..5] @ +48
constexpr uint32_t SRS     = 196736;   // 4 x 128 float partial rowsums
constexpr uint32_t SINV    = 198784;   // 128 float inverse sums
constexpr uint32_t SMEM_SZ = 199424;

DI uint32_t s2u(const void* p) {
    uint32_t a;
    asm("{ .reg .u64 t; cvta.to.shared.u64 t, %1; cvt.u32.u64 %0, t; }" : "=r"(a) : "l"(p));
    return a;
}
DI void cpa16(uint32_t d, const void* g) {
    asm volatile("cp.async.cg.shared.global [%0], [%1], 16;" :: "r"(d), "l"(g));
}
DI void cpa_commit() { asm volatile("cp.async.commit_group;" ::: "memory"); }
template <int N> DI void cpa_wait() {
    asm volatile("cp.async.wait_group %0;" :: "n"(N) : "memory");
}
DI void mbar_init(uint32_t a, uint32_t cnt) {
    asm volatile("mbarrier.init.shared.b64 [%0], %1;" :: "r"(a), "r"(cnt) : "memory");
}
DI void mbar_arrive(uint32_t a) {
    asm volatile("mbarrier.arrive.shared.b64 _, [%0];" :: "r"(a) : "memory");
}
// .noinc is load-bearing (R10 hang): default form nets zero against init count.
DI void cpa_mbar_arrive(uint32_t a) {
    asm volatile("cp.async.mbarrier.arrive.noinc.shared.b64 [%0];" :: "r"(a) : "memory");
}
DI void mbar_wait(uint32_t a, uint32_t ph) {
    asm volatile(
        "{\n\t.reg .pred P;\n"
        "LW%=:\n\t"
        "mbarrier.try_wait.parity.acquire.cta.shared::cta.b64 P, [%0], %1, 0x989680;\n\t"
        "@P bra LD%=;\n\t"
        "bra LW%=;\n"
        "LD%=:\n\t}" :: "r"(a), "r"(ph) : "memory");
}
// 2-wide exp2 on MUFU: fp16 quantization identical in both passes -> consistent.
DI float2 exp2_pair(float a, float b) {
    __half2 h = __floats2half2_rn(a, b);
    uint32_t u = *reinterpret_cast<uint32_t*>(&h);
    uint32_t o;
    asm("ex2.approx.f16x2 %0, %1;" : "=r"(o) : "r"(u));
    __half2 ho = *reinterpret_cast<__half2*>(&o);
    return __half22float2(ho);
}
DI void stcs2(float* p, float x, float y) {
    asm volatile("st.global.cs.v2.f32 [%0], {%1,%2};" :: "l"(p), "f"(x), "f"(y) : "memory");
}
DI void ldsm4(uint32_t* r, uint32_t a) {
    asm volatile("ldmatrix.sync.aligned.m8n8.x4.shared.b16 {%0,%1,%2,%3}, [%4];"
                 : "=r"(r[0]), "=r"(r[1]), "=r"(r[2]), "=r"(r[3]) : "r"(a));
}
DI void ldsm4t(uint32_t* r, uint32_t a) {
    asm volatile("ldmatrix.sync.aligned.m8n8.x4.trans.shared.b16 {%0,%1,%2,%3}, [%4];"
                 : "=r"(r[0]), "=r"(r[1]), "=r"(r[2]), "=r"(r[3]) : "r"(a));
}
DI void mma16816(float* d, const uint32_t* a, const uint32_t* b) {
    asm volatile(
        "mma.sync.aligned.m16n8k16.row.col.f32.f16.f16.f32 "
        "{%0,%1,%2,%3}, {%4,%5,%6,%7}, {%8,%9}, {%0,%1,%2,%3};"
        : "+f"(d[0]), "+f"(d[1]), "+f"(d[2]), "+f"(d[3])
        : "r"(a[0]), "r"(a[1]), "r"(a[2]), "r"(a[3]), "r"(b[0]), "r"(b[1]));
}

// A tile (one-time): 128 rows x 128 k, 256B rows, chunk16 swizzle c ^= row&7.
DI void load_A(uint32_t base, int t0, int tid) {
#pragma unroll
    for (int j = 0; j < 4; ++j) {
        int ch = tid + j * THREADS;
        int row = ch >> 4, c = ch & 15;
        int csw = c ^ (row & 7);
        cpa16(base + (uint32_t)(row * 256 + csw * 16),
              g_ft + (size_t)(t0 + row) * C + c * 8);
    }
}
// B tile streaming: fully precomputed per-thread addressing (R13).
DI void load_B_fast(uint32_t slot_base, uint32_t dstoff, const __half* src) {
#pragma unroll
    for (int j = 0; j < 4; ++j)
        cpa16(slot_base + dstoff + (uint32_t)(j * 8192), src + (size_t)j * 32 * R);
}

__global__ void __launch_bounds__(THREADS, 1) affinity_main(float* __restrict__ out) {
    extern __shared__ char smem[];
    uint32_t sb = s2u(smem);
    int tid = threadIdx.x, l = tid & 31, wid = tid >> 5;
    int wm = wid & 3, wn = wid >> 2;                  // 4M x 4N warps; warp tile 32x32
    int n = blockIdx.x >> 5, t0 = (blockIdx.x & 31) << 7;

    int moff = (l & 7) + ((l >> 3) & 1) * 8;
    int cgrp = l >> 4;
    int rm = l & 7;

    if (tid == 0) {
#pragma unroll
        for (int s = 0; s < NSLOT; ++s) {
            mbar_init(sb + SMBAR + (uint32_t)s * 8, THREADS);        // full
            mbar_init(sb + SMBAR + 48 + (uint32_t)s * 8, 16);        // empty
        }
    }
    __syncthreads();

    // ---- stage A through slot 0, extract to registers ----
    load_A(sb, t0, tid);
    cpa_commit();
    cpa_wait<0>();
    __syncthreads();

    uint32_t aR[8][2][4];                             // 64 regs
#pragma unroll
    for (int ks = 0; ks < 8; ++ks)
#pragma unroll
        for (int mf = 0; mf < 2; ++mf)
            ldsm4(aR[ks][mf],
                  sb + (uint32_t)((wm * 32 + mf * 16 + moff) * 256)
                     + (uint32_t)(((ks * 2 + cgrp) ^ rm) << 4));
    __syncthreads();                                  // A read done; barriers visible

    // ---- precomputed streaming addresses ----
    int k0 = tid >> 4, cc = tid & 15;
    uint32_t dstoff = (uint32_t)(k0 * 256 + (cc ^ (k0 & 7)) * 16);
    const __half* bsrc = g_fr + (size_t)n * C * R + (size_t)k0 * R + cc * 8;
    float* p0 = out + ((size_t)n * T + (size_t)(t0 + wm * 32 + (l >> 2))) * R
                    + wn * 32 + (l & 3) * 2;

    // ---- prologue: tiles 0..LEAD-1 into slots 0..LEAD-1 (vacuously empty) ----
#pragma unroll
    for (int p = 0; p < LEAD; ++p) {
        load_B_fast(sb + (uint32_t)p * SB_SZ, dstoff, bsrc + (size_t)p * 128);
        cpa_mbar_arrive(sb + SMBAR + (uint32_t)p * 8);
    }

    uint32_t bOff[2];
#pragma unroll
    for (int nf = 0; nf < 2; ++nf)
        bOff[nf] = (uint32_t)(moff * 256 + (((wn * 4 + nf * 2 + cgrp) ^ rm) << 4));

    float rsv[4];             // pass0: rowsums; pass1: inverses
#pragma unroll
    for (int i = 0; i < 4; ++i) rsv[i] = 0.f;

#pragma unroll 1
    for (int g = 0; g < NG; ++g) {
        uint32_t ug   = (uint32_t)g;
        uint32_t slot = ug % NSLOT;
        // consumer: full[slot] completes phase (g/6)&1 at the fill of tile g
        mbar_wait(sb + SMBAR + slot * 8, (ug / NSLOT) & 1u);

        float acc[2][4][4];
#pragma unroll
        for (int mf = 0; mf < 2; ++mf)
#pragma unroll
            for (int j8 = 0; j8 < 4; ++j8)
#pragma unroll
                for (int r = 0; r < 4; ++r) acc[mf][j8][r] = 0.f;

        uint32_t bb = sb + slot * SB_SZ;
#pragma unroll
        for (int ks = 0; ks < 8; ++ks) {
            uint32_t bf[2][4];
            ldsm4t(bf[0], bb + (uint32_t)(ks * 4096) + bOff[0]);
            ldsm4t(bf[1], bb + (uint32_t)(ks * 4096) + bOff[1]);
#pragma unroll
            for (int mf = 0; mf < 2; ++mf)
#pragma unroll
                for (int j8 = 0; j8 < 4; ++j8)
                    mma16816(acc[mf][j8], aR[ks][mf], &bf[j8 >> 1][(j8 & 1) * 2]);
        }
        if (l == 0) mbar_arrive(sb + SMBAR + 48 + slot * 8);   // release slot

        // producer: fill tile j = g+LEAD into slot j%6; first fill of each
        // slot (j<6) skips the empty-wait (vacuously free, R10 lesson).
        int j = g + LEAD;
        if (j < NG) {
            uint32_t uj = (uint32_t)j;
            uint32_t ps = uj % NSLOT;
            if (j >= NSLOT)
                mbar_wait(sb + SMBAR + 48 + ps * 8, ((uj / NSLOT) & 1u) ^ 1u);
            load_B_fast(sb + ps * SB_SZ, dstoff, bsrc + (size_t)(j & (NT - 1)) * 128);
            cpa_mbar_arrive(sb + SMBAR + ps * 8);
        }

        // epilogue — f16x2 MUFU; no CTA barrier, overlaps other warps' mainloops
        if (g < NT) {
#pragma unroll
            for (int mf = 0; mf < 2; ++mf) {
                float s0 = 0.f, s1 = 0.f;
#pragma unroll
                for (int j8 = 0; j8 < 4; ++j8) {
                    float2 e0 = exp2_pair(acc[mf][j8][0], acc[mf][j8][1]);
                    float2 e1 = exp2_pair(acc[mf][j8][2], acc[mf][j8][3]);
                    s0 += e0.x + e0.y;
                    s1 += e1.x + e1.y;
                }
                rsv[mf * 2 + 0] += s0;
                rsv[mf * 2 + 1] += s1;
            }
        } else {
            float* pt = p0 + (size_t)(g - NT) * 128;
#pragma unroll
            for (int mf = 0; mf < 2; ++mf) {
                float iv0 = rsv[mf * 2], iv1 = rsv[mf * 2 + 1];
#pragma unroll
                for (int j8 = 0; j8 < 4; ++j8) {
                    float2 e0 = exp2_pair(acc[mf][j8][0], acc[mf][j8][1]);
                    float2 e1 = exp2_pair(acc[mf][j8][2], acc[mf][j8][3]);
                    stcs2(pt + mf * 16 * R + j8 * 8,         e0.x * iv0, e0.y * iv0);
                    stcs2(pt + mf * 16 * R + 8 * R + j8 * 8, e1.x * iv1, e1.y * iv1);
                }
            }
        }

        // pass boundary: reduce rowsums -> inverses (warps re-converge once)
        if (g == NT - 1) {
#pragma unroll
            for (int i = 0; i < 4; ++i) {
                rsv[i] += __shfl_xor_sync(0xFFFFFFFFu, rsv[i], 1);
                rsv[i] += __shfl_xor_sync(0xFFFFFFFFu, rsv[i], 2);
            }
            float* rsp = (float*)(smem + SRS);
            if ((l & 3) == 0) {
#pragma unroll
                for (int mf = 0; mf < 2; ++mf)
#pragma unroll
                    for (int h = 0; h < 2; ++h) {
                        int row = wm * 32 + mf * 16 + (l >> 2) + h * 8;
                        rsp[wn * TM + row] = rsv[mf * 2 + h];
                    }
            }
            __syncthreads();
            float* sinv = (float*)(smem + SINV);
            if (tid < TM) {
                float s = rsp[tid] + rsp[TM + tid] + rsp[2 * TM + tid] + rsp[3 * TM + tid];
                sinv[tid] = 1.0f / s;
            }
            __syncthreads();
#pragma unroll
            for (int mf = 0; mf < 2; ++mf)
#pragma unroll
                for (int h = 0; h < 2; ++h)
                    rsv[mf * 2 + h] = sinv[wm * 32 + mf * 16 + (l >> 2) + h * 8];
        }
    }
}

// ---------------- fused normalization ----------------
__global__ void norm_all_kernel(const float* __restrict__ ft, const float* __restrict__ fr) {
    if (blockIdx.x < 512) {
        int row = blockIdx.x * 8 + (threadIdx.x >> 5);
        int lid = threadIdx.x & 31;
        const float* p = ft + (size_t)row * C;
        float v[4], s = 0.f;
#pragma unroll
        for (int j = 0; j < 4; ++j) { v[j] = p[lid + 32 * j]; s += v[j] * v[j]; }
#pragma unroll
        for (int o = 16; o > 0; o >>= 1) s += __shfl_xor_sync(0xFFFFFFFFu, s, o);
        float inv = 1.442695040888963f / fmaxf(sqrtf(s), 1e-12f);   // fold log2(e)
#pragma unroll
        for (int j = 0; j < 4; ++j)
            g_ft[(size_t)row * C + lid + 32 * j] = __float2half_rn(v[j] * inv);
    } else {
        int idx = (blockIdx.x - 512) * 256 + threadIdx.x;
        int n = idx >> 12, r = idx & (R - 1);
        const float* p = fr + (size_t)n * C * R + r;
        float s = 0.f;
#pragma unroll 4
        for (int k = 0; k < C; ++k) { float v = p[(size_t)k * R]; s += v * v; }
        float inv = 1.0f / fmaxf(sqrtf(s), 1e-12f);
#pragma unroll 4
        for (int k = 0; k < C; ++k)
            g_fr[(size_t)n * C * R + (size_t)k * R + r] = __float2half_rn(p[(size_t)k * R] * inv);
    }
}

extern "C" void kernel_launch(void* const* d_in, const int* in_sizes, int n_in,
                              void* d_out, int out_size) {
    const float* feat_tar  = (const float*)d_in[0];
    const float* feat_refs = (const float*)d_in[1];
    float* out = (float*)d_out;

    cudaFuncSetAttribute(affinity_main, cudaFuncAttributeMaxDynamicSharedMemorySize, SMEM_SZ);

    norm_all_kernel<<<512 + 128, 256>>>(feat_tar, feat_refs);
    affinity_main<<<NCTX * NMT, THREADS, SMEM_SZ>>>(out);
}

// round 16
// speedup vs baseline: 1.0474x; 1.0474x over previous
#include <cuda_runtime.h>
#include <cuda_fp16.h>
#include <cstdint>

#define DI __device__ __forceinline__

constexpr int C    = 128;
constexpr int T    = 4096;
constexpr int R    = 4096;
constexpr int NCTX = 8;
constexpr int TM   = 128;    // M rows per CTA
constexpr int NMT  = T / TM; // 32 m-tiles
constexpr int NTB  = 16;     // 256-wide BIG col tiles per pass
constexpr int NGB  = 2 * NTB; // pass0 + pass1, big-tile counter
constexpr int THREADS = 512;
constexpr int NSLOT = 3;     // big-slot ring depth
constexpr int LEAD  = 2;     // producer lead (big tiles)

// normalized fp16 features; g_ft pre-scaled by log2(e) so exp(dot) = ex2(acc)
__device__ __align__(256) __half g_ft[T * C];                    // 1 MB
__device__ __align__(256) __half g_fr[(size_t)NCTX * C * R];     // 8 MB (L2-resident)

// SMEM: 3 big slots (64 KB each = two 32 KB sub-tiles) + mbarriers + scratch
constexpr uint32_t SUB_SZ  = 32768;
constexpr uint32_t SLOT_SZ = 65536;
constexpr uint32_t SMBAR   = 196608;   // full[0..2] @ +0, empty[0..2] @ +24
constexpr uint32_t SRS     = 196736;   // 4 x 128 float partial rowsums
constexpr uint32_t SINV    = 198784;   // 128 float inverse sums
constexpr uint32_t SMEM_SZ = 199424;

DI uint32_t s2u(const void* p) {
    uint32_t a;
    asm("{ .reg .u64 t; cvta.to.shared.u64 t, %1; cvt.u32.u64 %0, t; }" : "=r"(a) : "l"(p));
    return a;
}
DI void cpa16(uint32_t d, const void* g) {
    asm volatile("cp.async.cg.shared.global [%0], [%1], 16;" :: "r"(d), "l"(g));
}
DI void cpa_commit() { asm volatile("cp.async.commit_group;" ::: "memory"); }
template <int N> DI void cpa_wait() {
    asm volatile("cp.async.wait_group %0;" :: "n"(N) : "memory");
}
DI void mbar_init(uint32_t a, uint32_t cnt) {
    asm volatile("mbarrier.init.shared.b64 [%0], %1;" :: "r"(a), "r"(cnt) : "memory");
}
DI void mbar_arrive(uint32_t a) {
    asm volatile("mbarrier.arrive.shared.b64 _, [%0];" :: "r"(a) : "memory");
}
// .noinc is load-bearing (R10 hang): default form nets zero against init count.
DI void cpa_mbar_arrive(uint32_t a) {
    asm volatile("cp.async.mbarrier.arrive.noinc.shared.b64 [%0];" :: "r"(a) : "memory");
}
DI void mbar_wait(uint32_t a, uint32_t ph) {
    asm volatile(
        "{\n\t.reg .pred P;\n"
        "LW%=:\n\t"
        "mbarrier.try_wait.parity.acquire.cta.shared::cta.b64 P, [%0], %1, 0x989680;\n\t"
        "@P bra LD%=;\n\t"
        "bra LW%=;\n"
        "LD%=:\n\t}" :: "r"(a), "r"(ph) : "memory");
}
// 2-wide exp2 on MUFU: fp16 quantization identical in both passes -> consistent.
DI float2 exp2_pair(float a, float b) {
    __half2 h = __floats2half2_rn(a, b);
    uint32_t u = *reinterpret_cast<uint32_t*>(&h);
    uint32_t o;
    asm("ex2.approx.f16x2 %0, %1;" : "=r"(o) : "r"(u));
    __half2 ho = *reinterpret_cast<__half2*>(&o);
    return __half22float2(ho);
}
DI void stcs2(float* p, float x, float y) {
    asm volatile("st.global.cs.v2.f32 [%0], {%1,%2};" :: "l"(p), "f"(x), "f"(y) : "memory");
}
DI void ldsm4(uint32_t* r, uint32_t a) {
    asm volatile("ldmatrix.sync.aligned.m8n8.x4.shared.b16 {%0,%1,%2,%3}, [%4];"
                 : "=r"(r[0]), "=r"(r[1]), "=r"(r[2]), "=r"(r[3]) : "r"(a));
}
DI void ldsm4t(uint32_t* r, uint32_t a) {
    asm volatile("ldmatrix.sync.aligned.m8n8.x4.trans.shared.b16 {%0,%1,%2,%3}, [%4];"
                 : "=r"(r[0]), "=r"(r[1]), "=r"(r[2]), "=r"(r[3]) : "r"(a));
}
DI void mma16816(float* d, const uint32_t* a, const uint32_t* b) {
    asm volatile(
        "mma.sync.aligned.m16n8k16.row.col.f32.f16.f16.f32 "
        "{%0,%1,%2,%3}, {%4,%5,%6,%7}, {%8,%9}, {%0,%1,%2,%3};"
        : "+f"(d[0]), "+f"(d[1]), "+f"(d[2]), "+f"(d[3])
        : "r"(a[0]), "r"(a[1]), "r"(a[2]), "r"(a[3]), "r"(b[0]), "r"(b[1]));
}

// A tile (one-time): 128 rows x 128 k, 256B rows, chunk16 swizzle c ^= row&7.
DI void load_A(uint32_t base, int t0, int tid) {
#pragma unroll
    for (int j = 0; j < 4; ++j) {
        int ch = tid + j * THREADS;
        int row = ch >> 4, c = ch & 15;
        int csw = c ^ (row & 7);
        cpa16(base + (uint32_t)(row * 256 + csw * 16),
              g_ft + (size_t)(t0 + row) * C + c * 8);
    }
}
// one 32KB sub-tile: fully precomputed per-thread addressing (R13).
DI void load_B_fast(uint32_t sub_base, uint32_t dstoff, const __half* src) {
#pragma unroll
    for (int j = 0; j < 4; ++j)
        cpa16(sub_base + dstoff + (uint32_t)(j * 8192), src + (size_t)j * 32 * R);
}
// big tile = two consecutive 128-col sub-tiles
DI void load_big(uint32_t slot_base, uint32_t dstoff, const __half* src) {
    load_B_fast(slot_base, dstoff, src);
    load_B_fast(slot_base + SUB_SZ, dstoff, src + 128);
}

__global__ void __launch_bounds__(THREADS, 1) affinity_main(float* __restrict__ out) {
    extern __shared__ char smem[];
    uint32_t sb = s2u(smem);
    int tid = threadIdx.x, l = tid & 31, wid = tid >> 5;
    int wm = wid & 3, wn = wid >> 2;                  // 4M x 4N warps; warp tile 32x32
    int n = blockIdx.x >> 5, t0 = (blockIdx.x & 31) << 7;

    int moff = (l & 7) + ((l >> 3) & 1) * 8;
    int cgrp = l >> 4;
    int rm = l & 7;

    if (tid == 0) {
#pragma unroll
        for (int s = 0; s < NSLOT; ++s) {
            mbar_init(sb + SMBAR + (uint32_t)s * 8, THREADS);        // full
            mbar_init(sb + SMBAR + 24 + (uint32_t)s * 8, 16);        // empty
        }
    }
    __syncthreads();

    // ---- stage A through slot 0, extract to registers ----
    load_A(sb, t0, tid);
    cpa_commit();
    cpa_wait<0>();
    __syncthreads();

    uint32_t aR[8][2][4];                             // 64 regs
#pragma unroll
    for (int ks = 0; ks < 8; ++ks)
#pragma unroll
        for (int mf = 0; mf < 2; ++mf)
            ldsm4(aR[ks][mf],
                  sb + (uint32_t)((wm * 32 + mf * 16 + moff) * 256)
                     + (uint32_t)(((ks * 2 + cgrp) ^ rm) << 4));
    __syncthreads();                                  // A read done; barriers visible

    // ---- precomputed streaming addresses ----
    int k0 = tid >> 4, cc = tid & 15;
    uint32_t dstoff = (uint32_t)(k0 * 256 + (cc ^ (k0 & 7)) * 16);
    const __half* bsrc = g_fr + (size_t)n * C * R + (size_t)k0 * R + cc * 8;
    float* p0 = out + ((size_t)n * T + (size_t)(t0 + wm * 32 + (l >> 2))) * R
                    + wn * 32 + (l & 3) * 2;

    // ---- prologue: big tiles 0,1 into slots 0,1 (vacuously empty) ----
#pragma unroll
    for (int p = 0; p < LEAD; ++p) {
        load_big(sb + (uint32_t)p * SLOT_SZ, dstoff, bsrc + (size_t)p * 256);
        cpa_mbar_arrive(sb + SMBAR + (uint32_t)p * 8);
    }

    uint32_t bOff[2];
#pragma unroll
    for (int nf = 0; nf < 2; ++nf)
        bOff[nf] = (uint32_t)(moff * 256 + (((wn * 4 + nf * 2 + cgrp) ^ rm) << 4));

    float rsv[4];             // pass0: rowsums; pass1: inverses
#pragma unroll
    for (int i = 0; i < 4; ++i) rsv[i] = 0.f;

#pragma unroll 1
    for (int g = 0; g < NGB; ++g) {
        uint32_t ug   = (uint32_t)g;
        uint32_t slot = ug % NSLOT;
        // consumer: fill #(g/3) of this slot completes phase (g/3)&1
        mbar_wait(sb + SMBAR + slot * 8, (ug / NSLOT) & 1u);

        // two 128-col halves per big tile, acc reused
#pragma unroll 1
        for (int h = 0; h < 2; ++h) {
            float acc[2][4][4];
#pragma unroll
            for (int mf = 0; mf < 2; ++mf)
#pragma unroll
                for (int j8 = 0; j8 < 4; ++j8)
#pragma unroll
                    for (int r = 0; r < 4; ++r) acc[mf][j8][r] = 0.f;

            uint32_t bb = sb + slot * SLOT_SZ + (uint32_t)h * SUB_SZ;
#pragma unroll
            for (int ks = 0; ks < 8; ++ks) {
                uint32_t bf[2][4];
                ldsm4t(bf[0], bb + (uint32_t)(ks * 4096) + bOff[0]);
                ldsm4t(bf[1], bb + (uint32_t)(ks * 4096) + bOff[1]);
#pragma unroll
                for (int mf = 0; mf < 2; ++mf)
#pragma unroll
                    for (int j8 = 0; j8 < 4; ++j8)
                        mma16816(acc[mf][j8], aR[ks][mf], &bf[j8 >> 1][(j8 & 1) * 2]);
            }

            if (g < NTB) {
#pragma unroll
                for (int mf = 0; mf < 2; ++mf) {
                    float s0 = 0.f, s1 = 0.f;
#pragma unroll
                    for (int j8 = 0; j8 < 4; ++j8) {
                        float2 e0 = exp2_pair(acc[mf][j8][0], acc[mf][j8][1]);
                        float2 e1 = exp2_pair(acc[mf][j8][2], acc[mf][j8][3]);
                        s0 += e0.x + e0.y;
                        s1 += e1.x + e1.y;
                    }
                    rsv[mf * 2 + 0] += s0;
                    rsv[mf * 2 + 1] += s1;
                }
            } else {
                float* pt = p0 + (size_t)((g - NTB) * 2 + h) * 128;
#pragma unroll
                for (int mf = 0; mf < 2; ++mf) {
                    float iv0 = rsv[mf * 2], iv1 = rsv[mf * 2 + 1];
#pragma unroll
                    for (int j8 = 0; j8 < 4; ++j8) {
                        float2 e0 = exp2_pair(acc[mf][j8][0], acc[mf][j8][1]);
                        float2 e1 = exp2_pair(acc[mf][j8][2], acc[mf][j8][3]);
                        stcs2(pt + mf * 16 * R + j8 * 8,         e0.x * iv0, e0.y * iv0);
                        stcs2(pt + mf * 16 * R + 8 * R + j8 * 8, e1.x * iv1, e1.y * iv1);
                    }
                }
            }
        }
        if (l == 0) mbar_arrive(sb + SMBAR + 24 + slot * 8);   // release slot

        // producer: fill big tile j = g+LEAD into slot j%3; first fill of each
        // slot (j<3) skips the empty-wait (vacuously free, R10 lesson).
        int j = g + LEAD;
        if (j < NGB) {
            uint32_t uj = (uint32_t)j;
            uint32_t ps = uj % NSLOT;
            if (j >= NSLOT)
                mbar_wait(sb + SMBAR + 24 + ps * 8, ((uj / NSLOT) & 1u) ^ 1u);
            load_big(sb + ps * SLOT_SZ, dstoff, bsrc + (size_t)(j & (NTB - 1)) * 256);
            cpa_mbar_arrive(sb + SMBAR + ps * 8);
        }

        // pass boundary: reduce rowsums -> inverses (warps re-converge once)
        if (g == NTB - 1) {
#pragma unroll
            for (int i = 0; i < 4; ++i) {
                rsv[i] += __shfl_xor_sync(0xFFFFFFFFu, rsv[i], 1);
                rsv[i] += __shfl_xor_sync(0xFFFFFFFFu, rsv[i], 2);
            }
            float* rsp = (float*)(smem + SRS);
            if ((l & 3) == 0) {
#pragma unroll
                for (int mf = 0; mf < 2; ++mf)
#pragma unroll
                    for (int h2 = 0; h2 < 2; ++h2) {
                        int row = wm * 32 + mf * 16 + (l >> 2) + h2 * 8;
                        rsp[wn * TM + row] = rsv[mf * 2 + h2];
                    }
            }
            __syncthreads();
            float* sinv = (float*)(smem + SINV);
            if (tid < TM) {
                float s = rsp[tid] + rsp[TM + tid] + rsp[2 * TM + tid] + rsp[3 * TM + tid];
                sinv[tid] = 1.0f / s;
            }
            __syncthreads();
#pragma unroll
            for (int mf = 0; mf < 2; ++mf)
#pragma unroll
                for (int h2 = 0; h2 < 2; ++h2)
                    rsv[mf * 2 + h2] = sinv[wm * 32 + mf * 16 + (l >> 2) + h2 * 8];
        }
    }
}

// ---------------- fused normalization ----------------
__global__ void norm_all_kernel(const float* __restrict__ ft, const float* __restrict__ fr) {
    if (blockIdx.x < 512) {
        int row = blockIdx.x * 8 + (threadIdx.x >> 5);
        int lid = threadIdx.x & 31;
        const float* p = ft + (size_t)row * C;
        float v[4], s = 0.f;
#pragma unroll
        for (int j = 0; j < 4; ++j) { v[j] = p[lid + 32 * j]; s += v[j] * v[j]; }
#pragma unroll
        for (int o = 16; o > 0; o >>= 1) s += __shfl_xor_sync(0xFFFFFFFFu, s, o);
        float inv = 1.442695040888963f / fmaxf(sqrtf(s), 1e-12f);   // fold log2(e)
#pragma unroll
        for (int j = 0; j < 4; ++j)
            g_ft[(size_t)row * C + lid + 32 * j] = __float2half_rn(v[j] * inv);
    } else {
        int idx = (blockIdx.x - 512) * 256 + threadIdx.x;
        int n = idx >> 12, r = idx & (R - 1);
        const float* p = fr + (size_t)n * C * R + r;
        float s = 0.f;
#pragma unroll 4
        for (int k = 0; k < C; ++k) { float v = p[(size_t)k * R]; s += v * v; }
        float inv = 1.0f / fmaxf(sqrtf(s), 1e-12f);
#pragma unroll 4
        for (int k = 0; k < C; ++k)
            g_fr[(size_t)n * C * R + (size_t)k * R + r] = __float2half_rn(p[(size_t)k * R] * inv);
    }
}

extern "C" void kernel_launch(void* const* d_in, const int* in_sizes, int n_in,
                              void* d_out, int out_size) {
    const float* feat_tar  = (const float*)d_in[0];
    const float* feat_refs = (const float*)d_in[1];
    float* out = (float*)d_out;

    cudaFuncSetAttribute(affinity_main, cudaFuncAttributeMaxDynamicSharedMemorySize, SMEM_SZ);

    norm_all_kernel<<<512 + 128, 256>>>(feat_tar, feat_refs);
    affinity_main<<<NCTX * NMT, THREADS, SMEM_SZ>>>(out);
}

// round 17
// speedup vs baseline: 1.0569x; 1.0090x over previous
#include <cuda_runtime.h>
#include <cuda_fp16.h>
#include <cstdint>

#define DI __device__ __forceinline__

constexpr int C    = 128;
constexpr int T    = 4096;
constexpr int R    = 4096;
constexpr int NCTX = 8;
constexpr int TM   = 128;    // M rows per CTA
constexpr int NMT  = T / TM; // 32 m-tiles
constexpr int NTB  = 16;     // 256-wide BIG col tiles per pass
constexpr int NGB  = 2 * NTB; // pass0 + pass1
constexpr int THREADS = 512;
constexpr int NSLOT = 3;     // big-slot ring depth
constexpr int LEAD  = 2;     // producer lead (big tiles)

// normalized fp16 features; g_ft pre-scaled by log2(e) so exp(dot) = ex2(acc)
__device__ __align__(256) __half g_ft[T * C];                    // 1 MB
__device__ __align__(256) __half g_fr[(size_t)NCTX * C * R];     // 8 MB (L2-resident)

constexpr uint32_t SUB_SZ  = 32768;
constexpr uint32_t SLOT_SZ = 65536;
constexpr uint32_t SMBAR   = 196608;   // full[0..2] @ +0, empty[0..2] @ +24
constexpr uint32_t SRS     = 196736;   // 4 x 128 float partial rowsums
constexpr uint32_t SINV    = 198784;   // 128 float inverse sums
constexpr uint32_t SMEM_SZ = 199424;

DI uint32_t s2u(const void* p) {
    uint32_t a;
    asm("{ .reg .u64 t; cvta.to.shared.u64 t, %1; cvt.u32.u64 %0, t; }" : "=r"(a) : "l"(p));
    return a;
}
DI void cpa16(uint32_t d, const void* g) {
    asm volatile("cp.async.cg.shared.global [%0], [%1], 16;" :: "r"(d), "l"(g));
}
DI void cpa_commit() { asm volatile("cp.async.commit_group;" ::: "memory"); }
template <int N> DI void cpa_wait() {
    asm volatile("cp.async.wait_group %0;" :: "n"(N) : "memory");
}
DI void mbar_init(uint32_t a, uint32_t cnt) {
    asm volatile("mbarrier.init.shared.b64 [%0], %1;" :: "r"(a), "r"(cnt) : "memory");
}
DI void mbar_arrive(uint32_t a) {
    asm volatile("mbarrier.arrive.shared.b64 _, [%0];" :: "r"(a) : "memory");
}
// .noinc is load-bearing (R10 hang): default form nets zero against init count.
DI void cpa_mbar_arrive(uint32_t a) {
    asm volatile("cp.async.mbarrier.arrive.noinc.shared.b64 [%0];" :: "r"(a) : "memory");
}
DI void mbar_wait(uint32_t a, uint32_t ph) {
    asm volatile(
        "{\n\t.reg .pred P;\n"
        "LW%=:\n\t"
        "mbarrier.try_wait.parity.acquire.cta.shared::cta.b64 P, [%0], %1, 0x989680;\n\t"
        "@P bra LD%=;\n\t"
        "bra LW%=;\n"
        "LD%=:\n\t}" :: "r"(a), "r"(ph) : "memory");
}
// 2-wide exp2 on MUFU: fp16 quantization identical in both passes -> consistent.
DI float2 exp2_pair(float a, float b) {
    __half2 h = __floats2half2_rn(a, b);
    uint32_t u = *reinterpret_cast<uint32_t*>(&h);
    uint32_t o;
    asm("ex2.approx.f16x2 %0, %1;" : "=r"(o) : "r"(u));
    __half2 ho = *reinterpret_cast<__half2*>(&o);
    return __half22float2(ho);
}
DI void stcs2(float* p, float x, float y) {
    asm volatile("st.global.cs.v2.f32 [%0], {%1,%2};" :: "l"(p), "f"(x), "f"(y) : "memory");
}
DI void ldsm4(uint32_t* r, uint32_t a) {
    asm volatile("ldmatrix.sync.aligned.m8n8.x4.shared.b16 {%0,%1,%2,%3}, [%4];"
                 : "=r"(r[0]), "=r"(r[1]), "=r"(r[2]), "=r"(r[3]) : "r"(a));
}
DI void ldsm4t(uint32_t* r, uint32_t a) {
    asm volatile("ldmatrix.sync.aligned.m8n8.x4.trans.shared.b16 {%0,%1,%2,%3}, [%4];"
                 : "=r"(r[0]), "=r"(r[1]), "=r"(r[2]), "=r"(r[3]) : "r"(a));
}
DI void mma16816(float* d, const uint32_t* a, const uint32_t* b) {
    asm volatile(
        "mma.sync.aligned.m16n8k16.row.col.f32.f16.f16.f32 "
        "{%0,%1,%2,%3}, {%4,%5,%6,%7}, {%8,%9}, {%0,%1,%2,%3};"
        : "+f"(d[0]), "+f"(d[1]), "+f"(d[2]), "+f"(d[3])
        : "r"(a[0]), "r"(a[1]), "r"(a[2]), "r"(a[3]), "r"(b[0]), "r"(b[1]));
}

// A tile (one-time): 128 rows x 128 k, 256B rows, chunk16 swizzle c ^= row&7.
DI void load_A(uint32_t base, int t0, int tid) {
#pragma unroll
    for (int j = 0; j < 4; ++j) {
        int ch = tid + j * THREADS;
        int row = ch >> 4, c = ch & 15;
        int csw = c ^ (row & 7);
        cpa16(base + (uint32_t)(row * 256 + csw * 16),
              g_ft + (size_t)(t0 + row) * C + c * 8);
    }
}
// one 32KB sub-tile: fully precomputed per-thread addressing (R13).
DI void load_B_fast(uint32_t sub_base, uint32_t dstoff, const __half* src) {
#pragma unroll
    for (int j = 0; j < 4; ++j)
        cpa16(sub_base + dstoff + (uint32_t)(j * 8192), src + (size_t)j * 32 * R);
}
// big tile = two consecutive 128-col sub-tiles
DI void load_big(uint32_t slot_base, uint32_t dstoff, const __half* src) {
    load_B_fast(slot_base, dstoff, src);
    load_B_fast(slot_base + SUB_SZ, dstoff, src + 128);
}

__global__ void __launch_bounds__(THREADS, 1) affinity_main(float* __restrict__ out) {
    extern __shared__ char smem[];
    uint32_t sb = s2u(smem);
    int tid = threadIdx.x, l = tid & 31, wid = tid >> 5;
    int wm = wid & 3, wn = wid >> 2;                  // 4M x 4N warps; warp tile 32x32
    int n = blockIdx.x >> 5, t0 = (blockIdx.x & 31) << 7;
    int hsw = wn & 1;                                 // R17: per-SMSP half-stagger
                                                      // (same-SMSP warps share wm, differ in wn)

    int moff = (l & 7) + ((l >> 3) & 1) * 8;
    int cgrp = l >> 4;
    int rm = l & 7;

    if (tid == 0) {
#pragma unroll
        for (int s = 0; s < NSLOT; ++s) {
            mbar_init(sb + SMBAR + (uint32_t)s * 8, THREADS);        // full
            mbar_init(sb + SMBAR + 24 + (uint32_t)s * 8, 16);        // empty
        }
    }
    __syncthreads();

    // ---- stage A through slot 0, extract to registers ----
    load_A(sb, t0, tid);
    cpa_commit();
    cpa_wait<0>();
    __syncthreads();

    uint32_t aR[8][2][4];                             // 64 regs
#pragma unroll
    for (int ks = 0; ks < 8; ++ks)
#pragma unroll
        for (int mf = 0; mf < 2; ++mf)
            ldsm4(aR[ks][mf],
                  sb + (uint32_t)((wm * 32 + mf * 16 + moff) * 256)
                     + (uint32_t)(((ks * 2 + cgrp) ^ rm) << 4));
    __syncthreads();                                  // A read done; barriers visible

    // ---- precomputed streaming addresses ----
    int k0 = tid >> 4, cc = tid & 15;
    uint32_t dstoff = (uint32_t)(k0 * 256 + (cc ^ (k0 & 7)) * 16);
    const __half* bsrc = g_fr + (size_t)n * C * R + (size_t)k0 * R + cc * 8;
    float* p0 = out + ((size_t)n * T + (size_t)(t0 + wm * 32 + (l >> 2))) * R
                    + wn * 32 + (l & 3) * 2;

    // ---- prologue: big tiles 0,1 into slots 0,1 (vacuously empty) ----
#pragma unroll
    for (int p = 0; p < LEAD; ++p) {
        load_big(sb + (uint32_t)p * SLOT_SZ, dstoff, bsrc + (size_t)p * 256);
        cpa_mbar_arrive(sb + SMBAR + (uint32_t)p * 8);
    }

    uint32_t bOff[2];
#pragma unroll
    for (int nf = 0; nf < 2; ++nf)
        bOff[nf] = (uint32_t)(moff * 256 + (((wn * 4 + nf * 2 + cgrp) ^ rm) << 4));

    float rsv[4];             // pass0: rowsums; pass1: inverses
#pragma unroll
    for (int i = 0; i < 4; ++i) rsv[i] = 0.f;

#pragma unroll 1
    for (int g = 0; g < NGB; ++g) {
        uint32_t ug   = (uint32_t)g;
        uint32_t slot = ug % NSLOT;
        // consumer: fill #(g/3) of this slot completes phase (g/3)&1
        mbar_wait(sb + SMBAR + slot * 8, (ug / NSLOT) & 1u);

        // two 128-col halves; odd-wn warps take them in reverse order so each
        // SMSP always has 2 warps in mainloop while 2 run epilogue (R17).
#pragma unroll 1
        for (int hh = 0; hh < 2; ++hh) {
            int h = hh ^ hsw;
            float acc[2][4][4];
#pragma unroll
            for (int mf = 0; mf < 2; ++mf)
#pragma unroll
                for (int j8 = 0; j8 < 4; ++j8)
#pragma unroll
                    for (int r = 0; r < 4; ++r) acc[mf][j8][r] = 0.f;

            uint32_t bb = sb + slot * SLOT_SZ + (uint32_t)h * SUB_SZ;
#pragma unroll
            for (int ks = 0; ks < 8; ++ks) {
                uint32_t bf[2][4];
                ldsm4t(bf[0], bb + (uint32_t)(ks * 4096) + bOff[0]);
                ldsm4t(bf[1], bb + (uint32_t)(ks * 4096) + bOff[1]);
#pragma unroll
                for (int mf = 0; mf < 2; ++mf)
#pragma unroll
                    for (int j8 = 0; j8 < 4; ++j8)
                        mma16816(acc[mf][j8], aR[ks][mf], &bf[j8 >> 1][(j8 & 1) * 2]);
            }

            if (g < NTB) {
#pragma unroll
                for (int mf = 0; mf < 2; ++mf) {
                    float s0 = 0.f, s1 = 0.f;
#pragma unroll
                    for (int j8 = 0; j8 < 4; ++j8) {
                        float2 e0 = exp2_pair(acc[mf][j8][0], acc[mf][j8][1]);
                        float2 e1 = exp2_pair(acc[mf][j8][2], acc[mf][j8][3]);
                        s0 += e0.x + e0.y;
                        s1 += e1.x + e1.y;
                    }
                    rsv[mf * 2 + 0] += s0;
                    rsv[mf * 2 + 1] += s1;
                }
            } else {
                float* pt = p0 + (size_t)((g - NTB) * 2 + h) * 128;
#pragma unroll
                for (int mf = 0; mf < 2; ++mf) {
                    float iv0 = rsv[mf * 2], iv1 = rsv[mf * 2 + 1];
#pragma unroll
                    for (int j8 = 0; j8 < 4; ++j8) {
                        float2 e0 = exp2_pair(acc[mf][j8][0], acc[mf][j8][1]);
                        float2 e1 = exp2_pair(acc[mf][j8][2], acc[mf][j8][3]);
                        stcs2(pt + mf * 16 * R + j8 * 8,         e0.x * iv0, e0.y * iv0);
                        stcs2(pt + mf * 16 * R + 8 * R + j8 * 8, e1.x * iv1, e1.y * iv1);
                    }
                }
            }
        }
        if (l == 0) mbar_arrive(sb + SMBAR + 24 + slot * 8);   // release slot

        // producer: fill big tile j = g+LEAD into slot j%3; first fill of each
        // slot (j<3) skips the empty-wait (vacuously free, R10 lesson).
        int j = g + LEAD;
        if (j < NGB) {
            uint32_t uj = (uint32_t)j;
            uint32_t ps = uj % NSLOT;
            if (j >= NSLOT)
                mbar_wait(sb + SMBAR + 24 + ps * 8, ((uj / NSLOT) & 1u) ^ 1u);
            load_big(sb + ps * SLOT_SZ, dstoff, bsrc + (size_t)(j & (NTB - 1)) * 256);
            cpa_mbar_arrive(sb + SMBAR + ps * 8);
        }

        // pass boundary: reduce rowsums -> inverses (warps re-converge once)
        if (g == NTB - 1) {
#pragma unroll
            for (int i = 0; i < 4; ++i) {
                rsv[i] += __shfl_xor_sync(0xFFFFFFFFu, rsv[i], 1);
                rsv[i] += __shfl_xor_sync(0xFFFFFFFFu, rsv[i], 2);
            }
            float* rsp = (float*)(smem + SRS);
            if ((l & 3) == 0) {
#pragma unroll
                for (int mf = 0; mf < 2; ++mf)
#pragma unroll
                    for (int h2 = 0; h2 < 2; ++h2) {
                        int row = wm * 32 + mf * 16 + (l >> 2) + h2 * 8;
                        rsp[wn * TM + row] = rsv[mf * 2 + h2];
                    }
            }
            __syncthreads();
            float* sinv = (float*)(smem + SINV);
            if (tid < TM) {
                float s = rsp[tid] + rsp[TM + tid] + rsp[2 * TM + tid] + rsp[3 * TM + tid];
                sinv[tid] = 1.0f / s;
            }
            __syncthreads();
#pragma unroll
            for (int mf = 0; mf < 2; ++mf)
#pragma unroll
                for (int h2 = 0; h2 < 2; ++h2)
                    rsv[mf * 2 + h2] = sinv[wm * 32 + mf * 16 + (l >> 2) + h2 * 8];
        }
    }
}

// ---------------- fused normalization ----------------
__global__ void norm_all_kernel(const float* __restrict__ ft, const float* __restrict__ fr) {
    if (blockIdx.x < 512) {
        int row = blockIdx.x * 8 + (threadIdx.x >> 5);
        int lid = threadIdx.x & 31;
        const float* p = ft + (size_t)row * C;
        float v[4], s = 0.f;
#pragma unroll
        for (int j = 0; j < 4; ++j) { v[j] = p[lid + 32 * j]; s += v[j] * v[j]; }
#pragma unroll
        for (int o = 16; o > 0; o >>= 1) s += __shfl_xor_sync(0xFFFFFFFFu, s, o);
        float inv = 1.442695040888963f / fmaxf(sqrtf(s), 1e-12f);   // fold log2(e)
#pragma unroll
        for (int j = 0; j < 4; ++j)
            g_ft[(size_t)row * C + lid + 32 * j] = __float2half_rn(v[j] * inv);
    } else {
        int idx = (blockIdx.x - 512) * 256 + threadIdx.x;
        int n = idx >> 12, r = idx & (R - 1);
        const float* p = fr + (size_t)n * C * R + r;
        float s = 0.f;
#pragma unroll 4
        for (int k = 0; k < C; ++k) { float v = p[(size_t)k * R]; s += v * v; }
        float inv = 1.0f / fmaxf(sqrtf(s), 1e-12f);
#pragma unroll 4
        for (int k = 0; k < C; ++k)
            g_fr[(size_t)n * C * R + (size_t)k * R + r] = __float2half_rn(p[(size_t)k * R] * inv);
    }
}

extern "C" void kernel_launch(void* const* d_in, const int* in_sizes, int n_in,
                              void* d_out, int out_size) {
    const float* feat_tar  = (const float*)d_in[0];
    const float* feat_refs = (const float*)d_in[1];
    float* out = (float*)d_out;

    cudaFuncSetAttribute(affinity_main, cudaFuncAttributeMaxDynamicSharedMemorySize, SMEM_SZ);

    norm_all_kernel<<<512 + 128, 256>>>(feat_tar, feat_refs);
    affinity_main<<<NCTX * NMT, THREADS, SMEM_SZ>>>(out);
}